// round 2
// baseline (speedup 1.0000x reference)
#include <cuda_runtime.h>
#include <math.h>

// Problem constants
#define Bn 16
#define An 3
#define Cn 80
#define Hn 76
#define Wn 76
#define Tn 50
#define TT   (Bn*Tn)          // 800 targets
#define HW   (Hn*Wn)          // 5776
#define HW4  (HW/4)           // 1444 float4 per plane
#define CH   (5+Cn)           // 85 channels per anchor
#define CHB  (An*CH)          // 255 channels per batch
#define NCELL (Bn*An*Hn*Wn)   // 277248
#define NCHUNK 6              // ceil(1444/256)
#define NPLANE (Bn*An)        // 48
#define NPART  (NPLANE*NCHUNK) // 288

// Scratch for dense partial sums (overwritten every launch -> no init kernel)
__device__ float g_partials[NPART];

__device__ __forceinline__ float sigm(float v){ return 1.0f/(1.0f+expf(-v)); }
// clip(log(p), -100): logf(0) = -inf -> fmaxf gives -100, matching jnp.clip
__device__ __forceinline__ float clog(float p){ return fmaxf(logf(p), -100.0f); }
__device__ __forceinline__ float bce(float p, float t){
    return -(t*clog(p) + (1.0f-t)*clog(1.0f-p));
}

// Block-wide sum; total valid on thread 0. Safe to call repeatedly.
__device__ float blockSum(float v, float* red){
    int lane = threadIdx.x & 31;
    int wid  = threadIdx.x >> 5;
    int nw   = (blockDim.x + 31) >> 5;
    #pragma unroll
    for (int o = 16; o > 0; o >>= 1) v += __shfl_down_sync(0xffffffffu, v, o);
    __syncthreads();                 // protect red reuse across calls
    if (lane == 0) red[wid] = v;
    __syncthreads();
    float r = 0.0f;
    if (wid == 0){
        r = (lane < nw) ? red[lane] : 0.0f;
        #pragma unroll
        for (int o = 16; o > 0; o >>= 1) r += __shfl_down_sync(0xffffffffu, r, o);
    }
    return r;
}

// ---------------------------------------------------------------------------
// Kernel A: dense sum of -clip(log(1 - sigmoid(conf))) over ALL cells.
// Only the conf channel (a*85+4) of each (b,a) plane is read: 1.1 MB total.
// float4-vectorized (plane base is 16B-aligned, HW divisible by 4).
// Per-block partial written to g_partials (overwrite semantics, no init).
// ---------------------------------------------------------------------------
__global__ void dense_conf_kernel(const float* __restrict__ inp){
    __shared__ float red[8];
    int plane = blockIdx.y;                 // 0..47  -> (b,a)
    int b = plane / An, a = plane % An;
    const float4* base = (const float4*)(inp + (size_t)(b*CHB + a*CH + 4) * HW);
    int idx  = blockIdx.x * blockDim.x + threadIdx.x;
    float v = 0.0f;
    if (idx < HW4){
        float4 p = base[idx];
        v  = -clog(1.0f - sigm(p.x));
        v += -clog(1.0f - sigm(p.y));
        v += -clog(1.0f - sigm(p.z));
        v += -clog(1.0f - sigm(p.w));
    }
    float tot = blockSum(v, red);
    if (threadIdx.x == 0) g_partials[plane * gridDim.x + blockIdx.x] = tot;
}

// ---------------------------------------------------------------------------
// Kernel B: everything else, single 1024-thread block.
//  Phase 1: per-target build (cell, best anchor, targets), hash-dedupe:
//           - winner map: cell -> max target idx (last-write-wins like scatter)
//           - noobj-zero set: (b,a,gj,gi) where iou > 0.5
//  Phase 2: per winning cell: gather 85 channels, compute all sparse losses;
//           class target = union of class bits of ALL targets at that cell
//           (matches multi-hot tcls scatter exactly).
//  Phase 3: subtract noobj-zero conf terms from dense total; count n_nm.
//  Phase 4: reduce dense partials, block-reduce, finalize 7 outputs.
// ---------------------------------------------------------------------------
__global__ void __launch_bounds__(1024) finalize_kernel(
        const float* __restrict__ inp,
        const float* __restrict__ tgt,
        float* __restrict__ out)
{
    __shared__ int    s_cell[TT];
    __shared__ int    s_cls[TT];
    __shared__ float4 s_txywh[TT];      // tx, ty, tw, th per target
    __shared__ int    s_best[TT];
    __shared__ int    wkey[1024];
    __shared__ int    wval[1024];
    __shared__ int    nkey[4096];
    __shared__ float  red[32];

    const float aw[3] = {1.25f, 2.0f, 4.125f};   // ANCHORS / STRIDE (608/76=8)
    const float ah[3] = {1.625f, 3.75f, 2.875f};

    int tid = threadIdx.x;

    // init tables
    wkey[tid] = 0; wval[tid] = -1;
    #pragma unroll
    for (int s = tid; s < 4096; s += 1024) nkey[s] = 0;
    if (tid < TT) s_cell[tid] = -1;
    __syncthreads();

    // ---- Phase 1: targets ----
    if (tid < TT){
        int t = tid;
        const float* tr = tgt + t*5;
        float c0 = tr[0], xx = tr[1], yy = tr[2], ww = tr[3], hh = tr[4];
        bool valid = (c0 + xx + yy + ww + hh) != 0.0f;
        float gx = xx*(float)Wn, gy = yy*(float)Hn;
        float gw = ww*(float)Wn, gh = hh*(float)Hn;
        int gi = (int)gx, gj = (int)gy;
        int b = t / Tn;
        float a1 = (gw + 1.0f)*(gh + 1.0f);
        float best_iou = -1.0f; int best = 0;
        float ious[3];
        #pragma unroll
        for (int a = 0; a < 3; a++){
            float inter = fmaxf(fminf(gw, aw[a]) + 1.0f, 0.0f)
                        * fmaxf(fminf(gh, ah[a]) + 1.0f, 0.0f);
            float iou = inter / (a1 + (aw[a]+1.0f)*(ah[a]+1.0f) - inter + 1e-16f);
            ious[a] = iou;
            if (iou > best_iou){ best_iou = iou; best = a; }   // first-max tie-break
        }
        bool ok = valid && gj >= 0 && gj < Hn && gi >= 0 && gi < Wn;
        s_cls[t]  = (int)c0;
        s_best[t] = best;
        s_txywh[t] = make_float4(gx - (float)gi,
                                 gy - (float)gj,
                                 logf(gw / aw[best] + 1e-16f),
                                 logf(gh / ah[best] + 1e-16f));
        if (ok){
            int cell = ((b*An + best)*Hn + gj)*Wn + gi;
            s_cell[t] = cell;
            unsigned key = (unsigned)cell + 1u;
            unsigned h = (key * 2654435761u) >> 22;   // 10-bit hash
            for (int probe = 0; probe < 1024; probe++){
                unsigned old = atomicCAS((unsigned*)&wkey[h], 0u, key);
                if (old == 0u || old == key){ atomicMax(&wval[h], t); break; }
                h = (h + 1u) & 1023u;
            }
        }
        if (valid){
            // clamp defensively for the noobj scatter address (matches mode='drop'
            // because in-distribution gi/gj are always in range)
            int cj = min(max(gj, 0), Hn-1);
            int ci = min(max(gi, 0), Wn-1);
            bool inb = (gj == cj) && (gi == ci);
            #pragma unroll
            for (int a = 0; a < 3; a++){
                if (inb && ious[a] > 0.5f){
                    int idx = ((b*An + a)*Hn + gj)*Wn + gi;
                    unsigned key = (unsigned)idx + 1u;
                    unsigned h = ((key * 2654435761u) >> 20) & 4095u;
                    for (int probe = 0; probe < 4096; probe++){
                        unsigned old = atomicCAS((unsigned*)&nkey[h], 0u, key);
                        if (old == 0u || old == key) break;
                        h = (h + 1u) & 4095u;
                    }
                }
            }
        }
    }
    __syncthreads();

    float sx=0.f, sy=0.f, sw_=0.f, sh_=0.f, sc1=0.f, scls=0.f, nm=0.f;
    float sub=0.f, cnt_no=0.f, t2=0.f;

    // ---- Phase 2: winning cells (one hash slot per thread) ----
    if (wkey[tid] != 0){
        int cell = wkey[tid] - 1;
        int t    = wval[tid];
        float4 txywh = s_txywh[t];
        int best = s_best[t];
        int b  = t / Tn;
        // decompose cell to (gj, gi): cell = ((b*A + best)*H + gj)*W + gi
        int gi = cell % Wn;
        int gj = (cell / Wn) % Hn;

        int base = (b*CHB + best*CH)*HW + gj*Wn + gi;
        float p0 = inp[base];
        float p1 = inp[base + HW];
        float p2 = inp[base + 2*HW];
        float p3 = inp[base + 3*HW];
        float p4 = inp[base + 4*HW];

        sx  = bce(sigm(p0), txywh.x);
        sy  = bce(sigm(p1), txywh.y);
        sw_ = (p2 - txywh.z)*(p2 - txywh.z);
        sh_ = (p3 - txywh.w)*(p3 - txywh.w);
        sc1 = -clog(sigm(p4));          // bce(conf, 1)
        nm  = 1.0f;

        // multi-hot class union over all targets mapping to this cell
        unsigned cm[3] = {0u, 0u, 0u};
        for (int u = 0; u < TT; u++){
            if (s_cell[u] == cell){
                int c = s_cls[u];
                if (c >= 0 && c < Cn) cm[c >> 5] |= (1u << (c & 31));
            }
        }
        #pragma unroll 8
        for (int c = 0; c < Cn; c++){
            float p = sigm(inp[base + (5 + c)*HW]);
            float tb = ((cm[c >> 5] >> (c & 31)) & 1u) ? 1.0f : 0.0f;
            scls += bce(p, tb);
        }
    }

    // ---- Phase 3: noobj-zero subtraction (4 slots per thread) ----
    #pragma unroll
    for (int s = tid; s < 4096; s += 1024){
        if (nkey[s] != 0){
            int idx = nkey[s] - 1;
            int i = idx % Wn; int r = idx / Wn;
            int j = r % Hn;   r /= Hn;
            int a = r % An;   int b = r / An;
            int addr = (b*CHB + a*CH + 4)*HW + j*Wn + i;
            float s_ = sigm(inp[addr]);
            sub    += -clog(1.0f - s_);
            cnt_no += 1.0f;
        }
    }

    // ---- Phase 4: dense partials ----
    if (tid < NPART) t2 = g_partials[tid];

    // ---- Reductions + finalize ----
    sx    = blockSum(sx, red);
    sy    = blockSum(sy, red);
    sw_   = blockSum(sw_, red);
    sh_   = blockSum(sh_, red);
    sc1   = blockSum(sc1, red);
    scls  = blockSum(scls, red);
    nm    = blockSum(nm, red);
    sub   = blockSum(sub, red);
    cnt_no= blockSum(cnt_no, red);
    t2    = blockSum(t2, red);

    if (tid == 0){
        float Nf   = (float)NCELL;
        float n_m  = nm;
        float n_nm = Nf - cnt_no;
        float term2 = t2 - sub;
        float lx = sx  / Nf / n_m;
        float ly = sy  / Nf / n_m;
        float lw = sw_ / Nf / n_m;
        float lh = sh_ / Nf / n_m;
        float lconf = sc1 / Nf / n_m + 0.5f * term2 / Nf / n_nm;
        float lcls  = scls / (n_m * (float)Cn) / n_m;
        float loss  = 2.5f*(lx + ly) + 2.5f*(lw + lh) + lconf + lcls;
        out[0] = loss;
        out[1] = lx;
        out[2] = ly;
        out[3] = lw;
        out[4] = lh;
        out[5] = lconf;
        out[6] = lcls;
    }
}

extern "C" void kernel_launch(void* const* d_in, const int* in_sizes, int n_in,
                              void* d_out, int out_size)
{
    const float* inp = (const float*)d_in[0];   // (B, A*(5+C), H, W) f32
    const float* tgt = (const float*)d_in[1];   // (B, T, 5) f32
    float* out = (float*)d_out;                 // 7 floats

    dim3 grid(NCHUNK, NPLANE, 1);               // 6 x 48 blocks, float4 path
    dense_conf_kernel<<<grid, 256>>>(inp);
    finalize_kernel<<<1, 1024>>>(inp, tgt, out);
}

// round 5
// speedup vs baseline: 3.6230x; 3.6230x over previous
#include <cuda_runtime.h>
#include <math.h>

// Problem constants
#define Bn 16
#define An 3
#define Cn 80
#define Hn 76
#define Wn 76
#define Tn 50
#define TT   (Bn*Tn)          // 800 targets
#define HW   (Hn*Wn)          // 5776
#define HW4  (HW/4)           // 1444 float4 per plane
#define CH   (5+Cn)           // 85 channels per anchor
#define CHB  (An*CH)          // 255
#define NCELL (Bn*An*Hn*Wn)   // 277248
#define NCHUNK 6              // ceil(1444/256)
#define NPLANE (Bn*An)        // 48
#define NDENSE (NPLANE*NCHUNK) // 288 dense blocks
#define NSPARSE 100           // 100 blocks * 8 warps = 800 warps (one per winner)
#define NNOOBJ 10             // 10 blocks * 256 = 2560 >= max 2400 noobj cells
#define NBLK (NDENSE + NSPARSE + NNOOBJ)   // 398

// ---- global scratch (all overwritten every launch; K1 zeroes accumulators) ----
__device__ float    g_partials[NDENSE];
__device__ float    g_acc[8];          // sx sy sw sh sc1 scls sub cnt_no
__device__ int      g_nwin;
__device__ int      g_nno;
__device__ int      g_win_base[1024];  // gather base addr per winner
__device__ float4   g_win_txywh[1024];
__device__ unsigned g_win_cm[1024][3]; // class bitmask per winning cell
__device__ int      g_no_addr[4096];   // conf addr per noobj-zero cell

__device__ __forceinline__ float sigm(float v){ return 1.0f/(1.0f+expf(-v)); }
__device__ __forceinline__ float clog(float p){ return fmaxf(logf(p), -100.0f); }
__device__ __forceinline__ float bce(float p, float t){
    return -(t*clog(p) + (1.0f-t)*clog(1.0f-p));
}

__device__ float blockSum(float v, float* red){
    int lane = threadIdx.x & 31;
    int wid  = threadIdx.x >> 5;
    int nw   = (blockDim.x + 31) >> 5;
    #pragma unroll
    for (int o = 16; o > 0; o >>= 1) v += __shfl_down_sync(0xffffffffu, v, o);
    __syncthreads();
    if (lane == 0) red[wid] = v;
    __syncthreads();
    float r = 0.0f;
    if (wid == 0){
        r = (lane < nw) ? red[lane] : 0.0f;
        #pragma unroll
        for (int o = 16; o > 0; o >>= 1) r += __shfl_down_sync(0xffffffffu, r, o);
    }
    return r;
}

__device__ __forceinline__ float warpSum(float v){
    #pragma unroll
    for (int o = 16; o > 0; o >>= 1) v += __shfl_down_sync(0xffffffffu, v, o);
    return v;
}

// ---------------------------------------------------------------------------
// K1: build targets, dedupe winners (last-write-wins via atomicMax on t),
//     class-union via atomicOr, noobj-zero set; compact lists to global.
// ---------------------------------------------------------------------------
__global__ void __launch_bounds__(1024) build_kernel(const float* __restrict__ tgt)
{
    __shared__ int      wkey[1024];
    __shared__ int      wval[1024];
    __shared__ unsigned wcm[1024][3];
    __shared__ int      nkey[4096];
    __shared__ float4   s_txywh[TT];
    __shared__ int      s_best[TT];

    const float aw[3] = {1.25f, 2.0f, 4.125f};   // ANCHORS / (608/76)
    const float ah[3] = {1.625f, 3.75f, 2.875f};

    int tid = threadIdx.x;
    wkey[tid] = 0; wval[tid] = -1;
    wcm[tid][0] = 0u; wcm[tid][1] = 0u; wcm[tid][2] = 0u;
    #pragma unroll
    for (int s = tid; s < 4096; s += 1024) nkey[s] = 0;
    if (tid == 0){ g_nwin = 0; g_nno = 0; }
    if (tid < 8) g_acc[tid] = 0.0f;
    __syncthreads();

    if (tid < TT){
        int t = tid;
        const float* tr = tgt + t*5;
        float c0 = tr[0], xx = tr[1], yy = tr[2], ww = tr[3], hh = tr[4];
        bool valid = (c0 + xx + yy + ww + hh) != 0.0f;
        float gx = xx*(float)Wn, gy = yy*(float)Hn;
        float gw = ww*(float)Wn, gh = hh*(float)Hn;
        int gi = (int)gx, gj = (int)gy;
        int b = t / Tn;
        float a1 = (gw + 1.0f)*(gh + 1.0f);
        float best_iou = -1.0f; int best = 0;
        float ious[3];
        #pragma unroll
        for (int a = 0; a < 3; a++){
            float inter = fmaxf(fminf(gw, aw[a]) + 1.0f, 0.0f)
                        * fmaxf(fminf(gh, ah[a]) + 1.0f, 0.0f);
            float iou = inter / (a1 + (aw[a]+1.0f)*(ah[a]+1.0f) - inter + 1e-16f);
            ious[a] = iou;
            if (iou > best_iou){ best_iou = iou; best = a; }
        }
        bool ok = valid && gj >= 0 && gj < Hn && gi >= 0 && gi < Wn;
        int cls = (int)c0;
        s_best[t]  = best;
        s_txywh[t] = make_float4(gx - (float)gi, gy - (float)gj,
                                 logf(gw / aw[best] + 1e-16f),
                                 logf(gh / ah[best] + 1e-16f));
        if (ok){
            int cell = ((b*An + best)*Hn + gj)*Wn + gi;
            unsigned key = (unsigned)cell + 1u;
            unsigned h = (key * 2654435761u) >> 22;
            for (int probe = 0; probe < 1024; probe++){
                unsigned old = atomicCAS((unsigned*)&wkey[h], 0u, key);
                if (old == 0u || old == key){
                    atomicMax(&wval[h], t);
                    if (cls >= 0 && cls < Cn)
                        atomicOr(&wcm[h][cls >> 5], 1u << (cls & 31));
                    break;
                }
                h = (h + 1u) & 1023u;
            }
        }
        if (valid && gj >= 0 && gj < Hn && gi >= 0 && gi < Wn){
            #pragma unroll
            for (int a = 0; a < 3; a++){
                if (ious[a] > 0.5f){
                    int idx = ((b*An + a)*Hn + gj)*Wn + gi;
                    unsigned key = (unsigned)idx + 1u;
                    unsigned h = ((key * 2654435761u) >> 20) & 4095u;
                    for (int probe = 0; probe < 4096; probe++){
                        unsigned old = atomicCAS((unsigned*)&nkey[h], 0u, key);
                        if (old == 0u || old == key) break;
                        h = (h + 1u) & 4095u;
                    }
                }
            }
        }
    }
    __syncthreads();

    // ---- compact winners ----
    if (wkey[tid] != 0){
        int cell = wkey[tid] - 1;
        int t    = wval[tid];
        int b    = t / Tn;
        int best = s_best[t];
        int gi = cell % Wn;
        int gj = (cell / Wn) % Hn;
        int pos = atomicAdd(&g_nwin, 1);
        g_win_base[pos]  = (b*CHB + best*CH)*HW + gj*Wn + gi;
        g_win_txywh[pos] = s_txywh[t];
        g_win_cm[pos][0] = wcm[tid][0];
        g_win_cm[pos][1] = wcm[tid][1];
        g_win_cm[pos][2] = wcm[tid][2];
    }
    // ---- compact noobj-zero cells ----
    #pragma unroll
    for (int s = tid; s < 4096; s += 1024){
        if (nkey[s] != 0){
            int idx = nkey[s] - 1;
            int i = idx % Wn; int r = idx / Wn;
            int j = r % Hn;   r /= Hn;
            int a = r % An;   int b = r / An;
            int pos = atomicAdd(&g_nno, 1);
            g_no_addr[pos] = (b*CHB + a*CH + 4)*HW + j*Wn + i;
        }
    }
}

// ---------------------------------------------------------------------------
// K2: fused worker.
//   blocks [0, 288):       dense conf partial sums (float4)
//   blocks [288, 388):     one warp per winning cell -> sparse losses
//   blocks [388, 398):     noobj-zero conf subtraction
// ---------------------------------------------------------------------------
__global__ void __launch_bounds__(256) worker_kernel(const float* __restrict__ inp)
{
    __shared__ float red[8];
    int bid = blockIdx.x;
    int tid = threadIdx.x;

    if (bid < NDENSE){
        int plane = bid / NCHUNK, chunk = bid % NCHUNK;
        int b = plane / An, a = plane % An;
        const float4* base = (const float4*)(inp + (size_t)(b*CHB + a*CH + 4) * HW);
        int idx = chunk * 256 + tid;
        float v = 0.0f;
        if (idx < HW4){
            float4 p = base[idx];
            v  = -clog(1.0f - sigm(p.x));
            v += -clog(1.0f - sigm(p.y));
            v += -clog(1.0f - sigm(p.z));
            v += -clog(1.0f - sigm(p.w));
        }
        float tot = blockSum(v, red);
        if (tid == 0) g_partials[bid] = tot;
    }
    else if (bid < NDENSE + NSPARSE){
        int w    = (bid - NDENSE) * 8 + (tid >> 5);   // global warp id = winner id
        int lane = tid & 31;
        if (w < g_nwin){
            int base     = g_win_base[w];
            float4 txywh = g_win_txywh[w];
            unsigned cm0 = g_win_cm[w][0], cm1 = g_win_cm[w][1], cm2 = g_win_cm[w][2];
            float sx=0.f, sy=0.f, sw_=0.f, sh_=0.f, sc1=0.f, scls=0.f;
            #pragma unroll
            for (int ci = 0; ci < 3; ci++){
                int ch = lane + ci*32;
                if (ch < CH){
                    float p = inp[base + ch*HW];
                    if (ch == 0)      sx  = bce(sigm(p), txywh.x);
                    else if (ch == 1) sy  = bce(sigm(p), txywh.y);
                    else if (ch == 2) sw_ = (p - txywh.z)*(p - txywh.z);
                    else if (ch == 3) sh_ = (p - txywh.w)*(p - txywh.w);
                    else if (ch == 4) sc1 = -clog(sigm(p));
                    else {
                        int c = ch - 5;
                        unsigned m = (c < 32) ? cm0 : (c < 64) ? cm1 : cm2;
                        float tb = ((m >> (c & 31)) & 1u) ? 1.0f : 0.0f;
                        scls += bce(sigm(p), tb);   // FIX: accumulate (was '=')
                    }
                }
            }
            sx   = warpSum(sx);   sy   = warpSum(sy);
            sw_  = warpSum(sw_);  sh_  = warpSum(sh_);
            sc1  = warpSum(sc1);  scls = warpSum(scls);
            if (lane == 0){
                atomicAdd(&g_acc[0], sx);
                atomicAdd(&g_acc[1], sy);
                atomicAdd(&g_acc[2], sw_);
                atomicAdd(&g_acc[3], sh_);
                atomicAdd(&g_acc[4], sc1);
                atomicAdd(&g_acc[5], scls);
            }
        }
    }
    else {
        int n = (bid - NDENSE - NSPARSE) * 256 + tid;
        float sub = 0.0f, cnt = 0.0f;
        if (n < g_nno){
            float s = sigm(inp[g_no_addr[n]]);
            sub = -clog(1.0f - s);
            cnt = 1.0f;
        }
        sub = blockSum(sub, red);
        cnt = blockSum(cnt, red);
        if (tid == 0 && (sub != 0.0f || cnt != 0.0f)){
            atomicAdd(&g_acc[6], sub);
            atomicAdd(&g_acc[7], cnt);
        }
    }
}

// ---------------------------------------------------------------------------
// K3: reduce dense partials + finalize 7 outputs.
// ---------------------------------------------------------------------------
__global__ void __launch_bounds__(512) final_kernel(float* __restrict__ out)
{
    __shared__ float red[16];
    int tid = threadIdx.x;
    float t2 = (tid < NDENSE) ? g_partials[tid] : 0.0f;
    t2 = blockSum(t2, red);
    if (tid == 0){
        float Nf    = (float)NCELL;
        float n_m   = (float)g_nwin;
        float n_nm  = Nf - g_acc[7];
        float term2 = t2 - g_acc[6];
        float lx = g_acc[0] / Nf / n_m;
        float ly = g_acc[1] / Nf / n_m;
        float lw = g_acc[2] / Nf / n_m;
        float lh = g_acc[3] / Nf / n_m;
        float lconf = g_acc[4] / Nf / n_m + 0.5f * term2 / Nf / n_nm;
        float lcls  = g_acc[5] / (n_m * (float)Cn) / n_m;
        float loss  = 2.5f*(lx + ly) + 2.5f*(lw + lh) + lconf + lcls;
        out[0] = loss;
        out[1] = lx;
        out[2] = ly;
        out[3] = lw;
        out[4] = lh;
        out[5] = lconf;
        out[6] = lcls;
    }
}

extern "C" void kernel_launch(void* const* d_in, const int* in_sizes, int n_in,
                              void* d_out, int out_size)
{
    const float* inp = (const float*)d_in[0];   // (B, A*(5+C), H, W) f32
    const float* tgt = (const float*)d_in[1];   // (B, T, 5) f32
    float* out = (float*)d_out;                 // 7 floats

    build_kernel<<<1, 1024>>>(tgt);
    worker_kernel<<<NBLK, 256>>>(inp);
    final_kernel<<<1, 512>>>(out);
}